// round 2
// baseline (speedup 1.0000x reference)
#include <cuda_runtime.h>
#include <cstdint>

#define NN 25000
#define NE 400000
#define FEAT 128
#define HID 64
#define HEADS 4
#define NCLS 2
#define NGRAPH 64

// ---------------- scratch (device globals; no allocation) ----------------
__device__ alignas(16) float g_xr1 [NN * 64];          // x @ W1_rel   (reused as xr5)
__device__ alignas(16) float g_acc1[NN * 64];          // x @ W1_root + b1, then +=agg (reused as acc5)
__device__ alignas(16) float g_xl  [(size_t)NN * 256]; // h1r @ Wg, later reused for h2
__device__ alignas(16) float g_S   [(size_t)NN * 256]; // GAT unnormalized weighted sum
__device__ alignas(16) float g_as  [NN * 4];
__device__ alignas(16) float g_ad  [NN * 4];
__device__ alignas(16) float g_mf  [NN * 4];
__device__ alignas(16) float g_den [NN * 4];
__device__ alignas(16) unsigned g_menc[NN * 4];
__device__ alignas(16) float g_pool[NGRAPH * HID];

// ---------------- helpers ----------------
__device__ __forceinline__ float lrelu(float x) { return x > 0.f ? x : 0.2f * x; }

// monotonic float <-> uint encode for atomicMax
__device__ __forceinline__ unsigned fenc(float f) {
    unsigned u = __float_as_uint(f);
    return (u & 0x80000000u) ? ~u : (u | 0x80000000u);
}
__device__ __forceinline__ float fdec(unsigned u) {
    return __uint_as_float((u & 0x80000000u) ? (u & 0x7fffffffu) : ~u);
}

__device__ __forceinline__ void red4(float* p, float4 v) {
    asm volatile("red.global.add.v4.f32 [%0], {%1,%2,%3,%4};"
                 :: "l"(p), "f"(v.x), "f"(v.y), "f"(v.z), "f"(v.w) : "memory");
}

// ---------------- generic SGEMM: C[M,N] = (reluA?relu(A):A)[M,K] @ B[K,N] (+bias) ----------------
// BM=64, BN=64, BK=16, 256 threads, 4x4 per thread
__global__ void sgemm_kernel(const float* __restrict__ A, const float* __restrict__ B,
                             float* __restrict__ C, int M, int N, int K,
                             const float* __restrict__ bias, int reluA)
{
    __shared__ float As[16][64];
    __shared__ float Bs[16][64];
    int tid = threadIdx.x;
    int row0 = blockIdx.y * 64, col0 = blockIdx.x * 64;
    int tx = tid & 15, ty = tid >> 4;
    int aRow = tid >> 2;          // 0..63
    int aK   = (tid & 3) * 4;     // 0,4,8,12
    int bK   = tid >> 4;          // 0..15
    int bCol = (tid & 15) * 4;    // 0..60

    float acc[4][4];
#pragma unroll
    for (int i = 0; i < 4; i++)
#pragma unroll
        for (int j = 0; j < 4; j++) acc[i][j] = 0.f;

    for (int k0 = 0; k0 < K; k0 += 16) {
        float4 av = make_float4(0.f, 0.f, 0.f, 0.f);
        int r = row0 + aRow;
        if (r < M) av = *(const float4*)(A + (size_t)r * K + k0 + aK);
        if (reluA) {
            av.x = fmaxf(av.x, 0.f); av.y = fmaxf(av.y, 0.f);
            av.z = fmaxf(av.z, 0.f); av.w = fmaxf(av.w, 0.f);
        }
        As[aK + 0][aRow] = av.x; As[aK + 1][aRow] = av.y;
        As[aK + 2][aRow] = av.z; As[aK + 3][aRow] = av.w;

        float4 bv = *(const float4*)(B + (size_t)(k0 + bK) * N + col0 + bCol);
        *(float4*)&Bs[bK][bCol] = bv;
        __syncthreads();

#pragma unroll
        for (int k = 0; k < 16; k++) {
            float4 a4 = *(float4*)&As[k][ty * 4];
            float4 b4 = *(float4*)&Bs[k][tx * 4];
            float ar[4] = {a4.x, a4.y, a4.z, a4.w};
            float br[4] = {b4.x, b4.y, b4.z, b4.w};
#pragma unroll
            for (int i = 0; i < 4; i++)
#pragma unroll
                for (int j = 0; j < 4; j++) acc[i][j] += ar[i] * br[j];
        }
        __syncthreads();
    }

#pragma unroll
    for (int i = 0; i < 4; i++) {
        int r = row0 + ty * 4 + i;
        if (r >= M) continue;
#pragma unroll
        for (int j = 0; j < 4; j++) {
            int c = col0 + tx * 4 + j;
            float v = acc[i][j];
            if (bias) v += bias[c];
            C[(size_t)r * N + c] = v;
        }
    }
}

// ---------------- conv edge scatter: g_acc1[dst] += g_xr1[src]  (64-dim) ----------------
__global__ void conv_edge_kernel(const int* __restrict__ src, const int* __restrict__ dst)
{
    int tid = blockIdx.x * 256 + threadIdx.x;
    int e = tid >> 4, t = tid & 15;
    if (e >= NE) return;
    int s = src[e], d = dst[e];
    float4 v = *(const float4*)(g_xr1 + (size_t)s * 64 + t * 4);
    red4(g_acc1 + (size_t)d * 64 + t * 4, v);
}

// ---------------- attention prep: a_s, a_d, init max with self-loop ----------------
__global__ void att_prep_kernel(const float* __restrict__ att_src, const float* __restrict__ att_dst)
{
    __shared__ float s_as[256], s_ad[256];
    int tid = threadIdx.x;
    if (tid < 256) { s_as[tid] = att_src[tid]; s_ad[tid] = att_dst[tid]; }
    __syncthreads();
    int warp = tid >> 5, lane = tid & 31;
    int n = blockIdx.x * 8 + warp;
    if (n >= NN) return;
    const float* xr = g_xl + (size_t)n * 256;
    float vs[4], vd[4];
#pragma unroll
    for (int h = 0; h < 4; h++) {
        float x0 = xr[h * 64 + lane], x1 = xr[h * 64 + lane + 32];
        float ps = x0 * s_as[h * 64 + lane] + x1 * s_as[h * 64 + lane + 32];
        float pd = x0 * s_ad[h * 64 + lane] + x1 * s_ad[h * 64 + lane + 32];
#pragma unroll
        for (int off = 16; off; off >>= 1) {
            ps += __shfl_down_sync(0xffffffffu, ps, off);
            pd += __shfl_down_sync(0xffffffffu, pd, off);
        }
        vs[h] = ps; vd[h] = pd;
    }
    if (lane == 0) {
#pragma unroll
        for (int h = 0; h < 4; h++) {
            g_as[n * 4 + h] = vs[h];
            g_ad[n * 4 + h] = vd[h];
            g_menc[n * 4 + h] = fenc(lrelu(vs[h] + vd[h]));   // self-loop seed
        }
    }
}

// ---------------- edge max pass ----------------
__global__ void edge_max_kernel(const int* __restrict__ src, const int* __restrict__ dst)
{
    int e = blockIdx.x * 256 + threadIdx.x;
    if (e >= NE) return;
    int s = src[e], d = dst[e];
    float4 a = *(const float4*)(g_as + s * 4);
    float4 b = *(const float4*)(g_ad + d * 4);
    float av[4] = {a.x, a.y, a.z, a.w}, bv[4] = {b.x, b.y, b.z, b.w};
#pragma unroll
    for (int h = 0; h < 4; h++)
        atomicMax(&g_menc[d * 4 + h], fenc(lrelu(av[h] + bv[h])));
}

// ---------------- init S/denom with self-loop contribution ----------------
__global__ void init_S_kernel()
{
    int idx = blockIdx.x * 256 + threadIdx.x;            // NN*256 threads
    int n = idx >> 8, c = idx & 255, h = c >> 6;
    float mf = fdec(g_menc[n * 4 + h]);
    float es = lrelu(g_as[n * 4 + h] + g_ad[n * 4 + h]);
    float p = expf(es - mf);
    g_S[idx] = p * g_xl[idx];
    if (c < 4) {
        float mfh = fdec(g_menc[n * 4 + c]);
        g_mf[n * 4 + c] = mfh;
        float e2 = lrelu(g_as[n * 4 + c] + g_ad[n * 4 + c]);
        g_den[n * 4 + c] = expf(e2 - mfh);
    }
}

// ---------------- GAT edge pass 2: S[dst] += p*xl[src], denom[dst] += p ----------------
__global__ void gat_edge_kernel(const int* __restrict__ src, const int* __restrict__ dst)
{
    int gt = blockIdx.x * 256 + threadIdx.x;
    int e = gt >> 5, lane = gt & 31;
    if (e >= NE) return;
    int s = src[e], d = dst[e];
    float asv = (lane < 4) ? g_as[s * 4 + lane] : 0.f;
    float adv = (lane < 4) ? g_ad[d * 4 + lane] : 0.f;
    float mv  = (lane < 4) ? g_mf[d * 4 + lane] : 0.f;

    int h1 = lane >> 4;            // 0 or 1
    int h2 = 2 + (lane >> 4);      // 2 or 3
    int hd = lane & 3;             // head for denom-lane

    // uniform shfl sequence across all lanes
    float e1 = lrelu(__shfl_sync(0xffffffffu, asv, h1) + __shfl_sync(0xffffffffu, adv, h1));
    float m1 = __shfl_sync(0xffffffffu, mv, h1);
    float e2 = lrelu(__shfl_sync(0xffffffffu, asv, h2) + __shfl_sync(0xffffffffu, adv, h2));
    float m2 = __shfl_sync(0xffffffffu, mv, h2);
    float ed = lrelu(__shfl_sync(0xffffffffu, asv, hd) + __shfl_sync(0xffffffffu, adv, hd));
    float md = __shfl_sync(0xffffffffu, mv, hd);

    float p1 = expf(e1 - m1);
    float p2 = expf(e2 - m2);
    float pd = expf(ed - md);

    const float* xr = g_xl + (size_t)s * 256;
    float* Sd = g_S + (size_t)d * 256;
    float4 v1 = *(const float4*)(xr + lane * 4);
    float4 v2 = *(const float4*)(xr + 128 + lane * 4);
    red4(Sd + lane * 4,       make_float4(p1 * v1.x, p1 * v1.y, p1 * v1.z, p1 * v1.w));
    red4(Sd + 128 + lane * 4, make_float4(p2 * v2.x, p2 * v2.y, p2 * v2.z, p2 * v2.w));
    if (lane < 4) atomicAdd(&g_den[d * 4 + lane], pd);
}

// ---------------- h2 = relu(S/denom + bg), written into g_xl ----------------
__global__ void h2_kernel(const float* __restrict__ bg)
{
    int idx = blockIdx.x * 256 + threadIdx.x;
    int n = idx >> 8, c = idx & 255, h = c >> 6;
    float v = g_S[idx] / g_den[n * 4 + h] + bg[c];
    g_xl[idx] = fmaxf(v, 0.f);
}

// ---------------- zero pool ----------------
__global__ void zero_pool_kernel()
{
    int t = blockIdx.x * 256 + threadIdx.x;
    if (t < NGRAPH * HID) g_pool[t] = 0.f;
}

// ---------------- pooling: g_pool[batch[n]] += relu(acc5[n])  (batch sorted) ----------------
__global__ void pool_kernel(const int* __restrict__ batch)
{
    int d = threadIdx.x & 63;
    int sub = threadIdx.x >> 6;
    int n0 = blockIdx.x * 64 + sub * 16;
    float sum = 0.f; int cur = -1;
#pragma unroll
    for (int i = 0; i < 16; i++) {
        int n = n0 + i;
        if (n >= NN) break;
        int b = batch[n];
        if (b != cur) {
            if (cur >= 0) atomicAdd(&g_pool[cur * 64 + d], sum);
            cur = b; sum = 0.f;
        }
        sum += fmaxf(g_acc1[(size_t)n * 64 + d], 0.f);
    }
    if (cur >= 0) atomicAdd(&g_pool[cur * 64 + d], sum);
}

// ---------------- head: relu(pool@Wfc1+b) @ Wfc2 + b -> sigmoid ----------------
__global__ void head_kernel(const float* __restrict__ Wfc1, const float* __restrict__ bfc1,
                            const float* __restrict__ Wfc2, const float* __restrict__ bfc2,
                            float* __restrict__ out)
{
    __shared__ float sg[64 * 64];
    __shared__ float sw[64 * 64];
    int t = threadIdx.x;
    for (int i = t; i < 4096; i += 256) { sg[i] = g_pool[i]; sw[i] = Wfc1[i]; }
    __syncthreads();
    float r[16];
#pragma unroll
    for (int i = 0; i < 16; i++) {
        int idx = t + 256 * i;
        int rr = idx >> 6, cc = idx & 63;
        float s = bfc1[cc];
#pragma unroll
        for (int k = 0; k < 64; k++) s += sg[rr * 64 + k] * sw[k * 64 + cc];
        r[i] = fmaxf(s, 0.f);
    }
    __syncthreads();
#pragma unroll
    for (int i = 0; i < 16; i++) sg[t + 256 * i] = r[i];
    __syncthreads();
    if (t < 128) {
        int rr = t >> 1, cc = t & 1;
        float s = bfc2[cc];
#pragma unroll
        for (int k = 0; k < 64; k++) s += sg[rr * 64 + k] * Wfc2[k * 2 + cc];
        out[t] = 1.f / (1.f + expf(-s));
    }
}

// ---------------- device-global accessor kernels avoid host symbol queries --------------
// (GEMMs need raw pointers to the globals; obtain them via a tiny setup kernel
//  writing addresses is overkill — instead wrap the GEMM launches with
//  dedicated entry kernels that alias the globals.)
__global__ void sgemm_xr1_from_x(const float* __restrict__ A, const float* __restrict__ B,
                                 int M, int N, int K) { }

// ---------------- launch ----------------
extern "C" void kernel_launch(void* const* d_in, const int* in_sizes, int n_in,
                              void* d_out, int out_size)
{
    const float* x       = (const float*)d_in[0];
    const int*   ei      = (const int*)d_in[1];
    const int*   batch   = (const int*)d_in[2];
    const float* W1_rel  = (const float*)d_in[3];
    const float* b1      = (const float*)d_in[4];
    const float* W1_root = (const float*)d_in[5];
    const float* Wg      = (const float*)d_in[6];
    const float* att_src = (const float*)d_in[7];
    const float* att_dst = (const float*)d_in[8];
    const float* bg      = (const float*)d_in[9];
    const float* W5_rel  = (const float*)d_in[10];
    const float* b5      = (const float*)d_in[11];
    const float* W5_root = (const float*)d_in[12];
    const float* W_fc1   = (const float*)d_in[13];
    const float* b_fc1   = (const float*)d_in[14];
    const float* W_fc2   = (const float*)d_in[15];
    const float* b_fc2   = (const float*)d_in[16];
    float* out = (float*)d_out;

    const int* src = ei;
    const int* dst = ei + NE;

    // Resolve device-global addresses once per process (cached host-side;
    // cudaGetSymbolAddress is a pure address query, but hoist it out of the
    // capture path anyway).
    static float *p_xr1 = nullptr, *p_acc1 = nullptr, *p_xl = nullptr;
    if (!p_xr1) {
        cudaGetSymbolAddress((void**)&p_xr1, g_xr1);
        cudaGetSymbolAddress((void**)&p_acc1, g_acc1);
        cudaGetSymbolAddress((void**)&p_xl, g_xl);
    }

    dim3 g64(1, (NN + 63) / 64);
    dim3 g256(4, (NN + 63) / 64);

    zero_pool_kernel<<<16, 256>>>();

    // conv1: transform then aggregate
    sgemm_kernel<<<g64, 256>>>(x, W1_rel, p_xr1, NN, 64, FEAT, nullptr, 0);
    sgemm_kernel<<<g64, 256>>>(x, W1_root, p_acc1, NN, 64, FEAT, b1, 0);
    conv_edge_kernel<<<(NE * 16 + 255) / 256, 256>>>(src, dst);

    // GAT: xl = relu(h1) @ Wg
    sgemm_kernel<<<g256, 256>>>(p_acc1, Wg, p_xl, NN, 256, 64, nullptr, 1);
    att_prep_kernel<<<(NN + 7) / 8, 256>>>(att_src, att_dst);
    edge_max_kernel<<<(NE + 255) / 256, 256>>>(src, dst);
    init_S_kernel<<<NN, 256>>>();
    gat_edge_kernel<<<(NE * 32 + 255) / 256, 256>>>(src, dst);
    h2_kernel<<<NN, 256>>>(bg);

    // conv5: transform then aggregate (reuse xr1/acc1 buffers)
    sgemm_kernel<<<g64, 256>>>(p_xl, W5_rel, p_xr1, NN, 64, 256, nullptr, 0);
    sgemm_kernel<<<g64, 256>>>(p_xl, W5_root, p_acc1, NN, 64, 256, b5, 0);
    conv_edge_kernel<<<(NE * 16 + 255) / 256, 256>>>(src, dst);

    // pool + head
    pool_kernel<<<(NN + 63) / 64, 256>>>(batch);
    head_kernel<<<1, 256>>>(W_fc1, b_fc1, W_fc2, b_fc2, out);
}